// round 12
// baseline (speedup 1.0000x reference)
#include <cuda_runtime.h>
#include <cuda_fp16.h>
#include <cstdint>

// Problem constants
#define BATCH 8
#define C 256
#define KB 4
#define HH 128
#define WW 128
#define HWS 16384
#define NPX (BATCH*HWS)

// ---------------- device scratch ----------------
__device__ __align__(16) __half g_projh[(size_t)NPX * C]; // proj fp16 [b][p][c]
__device__ __align__(16) __half g_w1[C * C];              // conv_w fp16 [o][c]
__device__ __align__(16) __half g_w2[C * C];              // BN-folded out_w fp16 [o][c]
__device__ float g_bias2[C];
__device__ float4 g_cw[(size_t)BATCH * KB * HWS];
__device__ int4   g_idx[(size_t)BATCH * KB * HWS];

// ---------------- helpers ----------------
__device__ __forceinline__ uint32_t smem_u32(const void* p) {
    uint32_t a;
    asm("{ .reg .u64 t; cvta.to.shared.u64 t, %1; cvt.u32.u64 %0, t; }" : "=r"(a) : "l"(p));
    return a;
}

__device__ __forceinline__ void ldsm4(uint32_t* r, uint32_t addr) {
    asm volatile("ldmatrix.sync.aligned.m8n8.x4.shared.b16 {%0,%1,%2,%3}, [%4];"
                 : "=r"(r[0]), "=r"(r[1]), "=r"(r[2]), "=r"(r[3]) : "r"(addr));
}

__device__ __forceinline__ void mma_fp16(float* d, const uint32_t* a, uint32_t b0, uint32_t b1) {
    asm volatile(
        "mma.sync.aligned.m16n8k16.row.col.f32.f16.f16.f32 "
        "{%0,%1,%2,%3}, {%4,%5,%6,%7}, {%8,%9}, {%0,%1,%2,%3};"
        : "+f"(d[0]), "+f"(d[1]), "+f"(d[2]), "+f"(d[3])
        : "r"(a[0]), "r"(a[1]), "r"(a[2]), "r"(a[3]), "r"(b0), "r"(b1));
}

// ============ GEMM1: tile 128x128, BK=32, 256 thr, 2 CTA/SM, aux fused ============
#define ROWB 80
#define TSZ  (128 * ROWB)
#define BUFSZ (2 * TSZ)
#define OFF_A  0
#define OFF_B  TSZ
#define OFF_BIAS (2 * BUFSZ)               // 81920, 512B used
#define OFF_WSI  (OFF_BIAS + 512)          // 82432, 12288B (C*12 floats)
#define GEMM_SMEM (OFF_WSI + C * 12 * 4)   // 94720

// ============ fused GEMM2: tile 128px x 256out, 512 thr, B dbl-buffered ============
#define A_PITCH 528
#define A_SZ (128 * A_PITCH)              // 67584
#define B_PITCH 48                        // 16 halves + 16B pad
#define B_TSZ (256 * B_PITCH)             // 12288
#define OFF2_B A_SZ
#define OFF2_BIAS (A_SZ + 2 * B_TSZ)      // 92160
#define GEMM2_SMEM (OFF2_BIAS + 1024)     // 93184

// ---------------- prep: weights to fp16, fold BN ----------------
__global__ void prep_kernel(const float* __restrict__ conv_w,
                            const float* __restrict__ out_w, const float* __restrict__ out_b,
                            const float* __restrict__ gamma, const float* __restrict__ beta,
                            const float* __restrict__ rmean, const float* __restrict__ rvar) {
    int o = blockIdx.x;
    int c = threadIdx.x;
    __shared__ float red[C];
    g_w1[o * C + c] = __float2half_rn(conv_w[o * C + c]);

    float inv = gamma[c] / sqrtf(rvar[c] + 1e-5f);
    float w = out_w[o * C + c];
    g_w2[o * C + c] = __float2half_rn(w * inv);

    red[c] = w * (beta[c] - rmean[c] * inv);
    __syncthreads();
    for (int s = 128; s > 0; s >>= 1) {
        if (c < s) red[c] += red[c + s];
        __syncthreads();
    }
    if (c == 0) g_bias2[o] = red[0] + out_b[o];
}

// ---------------- GEMM1 (+fused aux): proj = x^T @ conv_w^T + conv_b ----------------
struct PF1 {
    uint32_t a[8];
    int4 b[2];
};

__device__ __forceinline__ void pf1_load(PF1& f, const float* __restrict__ xb,
                                         const __half* __restrict__ w,
                                         int kc, int am, int ach, int tid) {
    float v[16];
#pragma unroll
    for (int i = 0; i < 16; i++) {
        int cl = ach * 16 + i;
        v[i] = xb[(size_t)(kc + cl) * HWS + am];
    }
#pragma unroll
    for (int i = 0; i < 8; i++) {
        __half2 h = __floats2half2_rn(v[2 * i], v[2 * i + 1]);
        f.a[i] = *reinterpret_cast<uint32_t*>(&h);
    }
#pragma unroll
    for (int j = 0; j < 2; j++) {
        int e = j * 256 + tid;
        int row = e >> 2, ch = e & 3;
        f.b[j] = *(const int4*)(w + (size_t)row * C + kc + ch * 8);
    }
}

__device__ __forceinline__ void pf1_store(const PF1& f, char* base, int am, int ach, int tid) {
#pragma unroll
    for (int i = 0; i < 8; i++) {
        int cl = ach * 16 + i * 2;
        *(uint32_t*)(base + OFF_A + am * ROWB + cl * 2) = f.a[i];
    }
#pragma unroll
    for (int j = 0; j < 2; j++) {
        int e = j * 256 + tid;
        int row = e >> 2, ch = e & 3;
        *(int4*)(base + OFF_B + row * ROWB + ch * 16) = f.b[j];
    }
}

__global__ __launch_bounds__(256) void gemm1_mma(const float* __restrict__ x,
                                                 const float* __restrict__ conv_b,
                                                 const float* __restrict__ off_w,
                                                 const float* __restrict__ off_b,
                                                 const float* __restrict__ wgt_w,
                                                 const float* __restrict__ wgt_b) {
    extern __shared__ char sm[];
    const uint32_t smb = smem_u32(sm);
    const int tid = threadIdx.x;
    const int wid = tid >> 5, lane = tid & 31;
    const int warp_m = wid & 3, warp_n = wid >> 2;
    const int lr = lane & 15, lc = lane >> 4;
    const int p0 = blockIdx.x * 128, o0 = blockIdx.y * 128, b = blockIdx.z;
    const bool doaux = (o0 == 0);

    if (tid < 128) ((float*)(sm + OFF_BIAS))[tid] = conv_b[o0 + tid];

    float* wsi = (float*)(sm + OFF_WSI);     // interleaved [c][12]
    float aacc[12];
    if (doaux) {
        for (int e = tid; e < 2 * C * KB; e += 256) {     // off_w: [(k*2+d)][c]
            int kd = e >> 8, c = e & 255;
            wsi[c * 12 + kd] = off_w[e];
        }
        for (int e = tid; e < C * KB; e += 256) {         // wgt_w: [k][c]
            int k = e >> 8, c = e & 255;
            wsi[c * 12 + 8 + k] = wgt_w[e];
        }
#pragma unroll
        for (int j = 0; j < 12; j++) aacc[j] = 0.f;
    }

    const float* xb = x + (size_t)b * C * HWS + p0;
    const __half* w = g_w1 + (size_t)o0 * C;
    const int am = tid & 127, ach = tid >> 7;

    float acc[2][8][4];
#pragma unroll
    for (int t = 0; t < 2; t++)
#pragma unroll
        for (int j = 0; j < 8; j++)
#pragma unroll
            for (int q = 0; q < 4; q++) acc[t][j][q] = 0.f;

    PF1 f;
    pf1_load(f, xb, w, 0, am, ach, tid);
    pf1_store(f, sm, am, ach, tid);
    __syncthreads();

    for (int kt = 0; kt < 8; kt++) {
        const int buf = kt & 1;
        if (kt < 7) pf1_load(f, xb, w, (kt + 1) * 32, am, ach, tid);
        {
            const uint32_t smbuf = smb + buf * BUFSZ;
            const uint32_t a_base = smbuf + OFF_A + (uint32_t)(warp_m * 32 + lr) * ROWB + lc * 16;
            const uint32_t b_base = smbuf + OFF_B + (uint32_t)(warp_n * 64 + lr) * ROWB + lc * 16;
#pragma unroll
            for (int s = 0; s < 2; s++) {
                uint32_t a[2][4], bb[4][4];
#pragma unroll
                for (int t = 0; t < 2; t++)
                    ldsm4(a[t], a_base + t * (16 * ROWB) + s * 32);
#pragma unroll
                for (int u = 0; u < 4; u++)
                    ldsm4(bb[u], b_base + u * (16 * ROWB) + s * 32);
#pragma unroll
                for (int t = 0; t < 2; t++)
#pragma unroll
                    for (int u = 0; u < 4; u++) {
                        mma_fp16(acc[t][u * 2], a[t], bb[u][0], bb[u][2]);
                        mma_fp16(acc[t][u * 2 + 1], a[t], bb[u][1], bb[u][3]);
                    }
            }
        }
        // fused aux: accumulate 12 per-pixel dot products on this chunk's
        // channels (lines are L1-resident from the prefetch one iteration ago)
        if (doaux && tid < 128) {
            const float* xa = xb + tid;
#pragma unroll 4
            for (int cc = 0; cc < 32; cc++) {
                const int c = kt * 32 + cc;
                float xv = xa[(size_t)c * HWS];
                const float4* wp = (const float4*)(wsi + c * 12);
                float4 wa = wp[0], wb = wp[1], wc = wp[2];
                aacc[0] = fmaf(xv, wa.x, aacc[0]);  aacc[1] = fmaf(xv, wa.y, aacc[1]);
                aacc[2] = fmaf(xv, wa.z, aacc[2]);  aacc[3] = fmaf(xv, wa.w, aacc[3]);
                aacc[4] = fmaf(xv, wb.x, aacc[4]);  aacc[5] = fmaf(xv, wb.y, aacc[5]);
                aacc[6] = fmaf(xv, wb.z, aacc[6]);  aacc[7] = fmaf(xv, wb.w, aacc[7]);
                aacc[8] = fmaf(xv, wc.x, aacc[8]);  aacc[9] = fmaf(xv, wc.y, aacc[9]);
                aacc[10] = fmaf(xv, wc.z, aacc[10]); aacc[11] = fmaf(xv, wc.w, aacc[11]);
            }
        }
        if (kt < 7) {
            pf1_store(f, sm + (buf ^ 1) * BUFSZ, am, ach, tid);
            __syncthreads();
        }
    }

    // fused aux finish: softmax + corner indices/weights
    if (doaux && tid < 128) {
        const int p = p0 + tid;
        const int py = p >> 7, px = p & 127;
        float l0 = aacc[8] + wgt_b[0], l1 = aacc[9] + wgt_b[1];
        float l2 = aacc[10] + wgt_b[2], l3 = aacc[11] + wgt_b[3];
        float mx = fmaxf(fmaxf(l0, l1), fmaxf(l2, l3));
        float e0 = __expf(l0 - mx), e1 = __expf(l1 - mx);
        float e2 = __expf(l2 - mx), e3 = __expf(l3 - mx);
        float invs = 1.f / (e0 + e1 + e2 + e3);
        float wk4[4] = {e0 * invs, e1 * invs, e2 * invs, e3 * invs};
#pragma unroll
        for (int k = 0; k < KB; k++) {
            float vx = (float)px + aacc[2 * k] + off_b[2 * k];
            float vy = (float)py + aacc[2 * k + 1] + off_b[2 * k + 1];
            float x0f = floorf(vx), y0f = floorf(vy);
            float wx1 = vx - x0f, wy1 = vy - y0f;
            int x0 = (int)x0f, y0 = (int)y0f;
            bool vx0 = (x0 >= 0) && (x0 <= WW - 1);
            bool vx1 = (x0 + 1 >= 0) && (x0 + 1 <= WW - 1);
            bool vy0 = (y0 >= 0) && (y0 <= HH - 1);
            bool vy1 = (y0 + 1 >= 0) && (y0 + 1 <= HH - 1);
            float wk = wk4[k];
            float w00 = (1.f - wx1) * (1.f - wy1) * wk * (float)(vx0 && vy0);
            float w01 = wx1 * (1.f - wy1) * wk * (float)(vx1 && vy0);
            float w10 = (1.f - wx1) * wy1 * wk * (float)(vx0 && vy1);
            float w11 = wx1 * wy1 * wk * (float)(vx1 && vy1);
            int xc0 = min(max(x0, 0), WW - 1);
            int xc1 = min(max(x0 + 1, 0), WW - 1);
            int yc0 = min(max(y0, 0), HH - 1);
            int yc1 = min(max(y0 + 1, 0), HH - 1);
            size_t off = ((size_t)(b * KB + k)) * HWS + p;
            g_idx[off] = make_int4(yc0 * WW + xc0, yc0 * WW + xc1,
                                   yc1 * WW + xc0, yc1 * WW + xc1);
            g_cw[off] = make_float4(w00, w01, w10, w11);
        }
    }

    // epilogue: write proj fp16 [b][p][o] + bias
    const float* sbias = (const float*)(sm + OFF_BIAS);
    __half* Cb = g_projh + ((size_t)b * HWS + p0) * C + o0;
    const int g4 = lane >> 2, tg = lane & 3;
#pragma unroll
    for (int t = 0; t < 2; t++) {
        const int r0 = warp_m * 32 + t * 16 + g4;
#pragma unroll
        for (int j = 0; j < 8; j++) {
            const int oc = warp_n * 64 + j * 8 + tg * 2;
            float b0 = sbias[oc], b1 = sbias[oc + 1];
            __half2 v0 = __floats2half2_rn(acc[t][j][0] + b0, acc[t][j][1] + b1);
            __half2 v1 = __floats2half2_rn(acc[t][j][2] + b0, acc[t][j][3] + b1);
            *(uint32_t*)(Cb + (size_t)r0 * C + oc) = *reinterpret_cast<uint32_t*>(&v0);
            *(uint32_t*)(Cb + (size_t)(r0 + 8) * C + oc) = *reinterpret_cast<uint32_t*>(&v1);
        }
    }
}

// ---------------- fused GEMM2: gather feat tile, then 128x256 GEMM ----------------
__device__ __forceinline__ void acc_row(float* acc, uint4 v, float w) {
    const __half2* h = reinterpret_cast<const __half2*>(&v);
#pragma unroll
    for (int i = 0; i < 4; i++) {
        float2 f = __half22float2(h[i]);
        acc[2 * i]     = fmaf(w, f.x, acc[2 * i]);
        acc[2 * i + 1] = fmaf(w, f.y, acc[2 * i + 1]);
    }
}

__global__ __launch_bounds__(512) void gemm2_fused(float* __restrict__ out) {
    extern __shared__ char sm[];
    const uint32_t smb = smem_u32(sm);
    const int tid = threadIdx.x;
    const int wid = tid >> 5, lane = tid & 31;
    const int warp_m = wid & 3, warp_n = wid >> 2;
    const int lr = lane & 15, lc = lane >> 4;
    const int p0 = blockIdx.x * 128, b = blockIdx.y;

    if (tid < 256) ((float*)(sm + OFF2_BIAS))[tid] = g_bias2[tid];

    // ---- gather phase: build feat A tile [128 px][256 ch] fp16 in smem ----
    const uint4* projb = (const uint4*)g_projh + (size_t)b * HWS * 32;
#pragma unroll
    for (int i = 0; i < 8; i++) {
        const int px = wid * 8 + i;
        const int p = p0 + px;
        const size_t kb = (size_t)b * KB * HWS + p;

        int4 id[KB];
        float4 w[KB];
#pragma unroll
        for (int k = 0; k < KB; k++) {
            id[k] = g_idx[kb + (size_t)k * HWS];
            w[k] = g_cw[kb + (size_t)k * HWS];
        }
        uint4 sv = projb[(size_t)p * 32 + lane];
        uint4 cv[KB * 4];
#pragma unroll
        for (int k = 0; k < KB; k++) {
            cv[k * 4 + 0] = projb[(size_t)id[k].x * 32 + lane];
            cv[k * 4 + 1] = projb[(size_t)id[k].y * 32 + lane];
            cv[k * 4 + 2] = projb[(size_t)id[k].z * 32 + lane];
            cv[k * 4 + 3] = projb[(size_t)id[k].w * 32 + lane];
        }
        float acc[8];
        {
            const __half2* h = reinterpret_cast<const __half2*>(&sv);
#pragma unroll
            for (int q = 0; q < 4; q++) {
                float2 f = __half22float2(h[q]);
                acc[2 * q] = f.x;
                acc[2 * q + 1] = f.y;
            }
        }
#pragma unroll
        for (int k = 0; k < KB; k++) {
            acc_row(acc, cv[k * 4 + 0], w[k].x);
            acc_row(acc, cv[k * 4 + 1], w[k].y);
            acc_row(acc, cv[k * 4 + 2], w[k].z);
            acc_row(acc, cv[k * 4 + 3], w[k].w);
        }
        __half2 o[4];
#pragma unroll
        for (int q = 0; q < 4; q++)
            o[q] = __floats2half2_rn(acc[2 * q], acc[2 * q + 1]);
        *(uint4*)(sm + px * A_PITCH + lane * 16) = *reinterpret_cast<uint4*>(o);
    }

    // ---- prefetch B chunk 0 ----
    const __half* w2 = g_w2;
    const int brow = tid >> 1, bch = tid & 1;
    int4 bv = *(const int4*)(w2 + (size_t)brow * C + bch * 8);
    *(int4*)(sm + OFF2_B + brow * B_PITCH + bch * 16) = bv;
    __syncthreads();

    float acc[2][8][4];
#pragma unroll
    for (int t = 0; t < 2; t++)
#pragma unroll
        for (int j = 0; j < 8; j++)
#pragma unroll
            for (int q = 0; q < 4; q++) acc[t][j][q] = 0.f;

    for (int kt = 0; kt < 16; kt++) {
        const int buf = kt & 1;
        if (kt < 15)
            bv = *(const int4*)(w2 + (size_t)brow * C + (kt + 1) * 16 + bch * 8);
        {
            const uint32_t a_base = smb + (uint32_t)(warp_m * 32 + lr) * A_PITCH + kt * 32 + lc * 16;
            const uint32_t b_base = smb + OFF2_B + buf * B_TSZ +
                                    (uint32_t)(warp_n * 64 + lr) * B_PITCH + lc * 16;
            uint32_t a[2][4], bb[4][4];
#pragma unroll
            for (int t = 0; t < 2; t++)
                ldsm4(a[t], a_base + t * (16 * A_PITCH));
#pragma unroll
            for (int u = 0; u < 4; u++)
                ldsm4(bb[u], b_base + u * (16 * B_PITCH));
#pragma unroll
            for (int t = 0; t < 2; t++)
#pragma unroll
                for (int u = 0; u < 4; u++) {
                    mma_fp16(acc[t][u * 2], a[t], bb[u][0], bb[u][2]);
                    mma_fp16(acc[t][u * 2 + 1], a[t], bb[u][1], bb[u][3]);
                }
        }
        if (kt < 15) {
            *(int4*)(sm + OFF2_B + (buf ^ 1) * B_TSZ + brow * B_PITCH + bch * 16) = bv;
            __syncthreads();
        }
    }

    // ---- epilogue: transpose through smem (reuse A region) -> out[b][o][p] ----
    __syncthreads();
    float* Cs = (float*)sm;   // 128 x 33 staging
    const float* sbias = (const float*)(sm + OFF2_BIAS);
    float* Ob = out + (size_t)b * C * HWS + p0;
    const int g4 = lane >> 2, tg = lane & 3;
#pragma unroll
    for (int g = 0; g < 8; g++) {
        if (warp_n == (g >> 1)) {
#pragma unroll
            for (int t = 0; t < 2; t++)
#pragma unroll
                for (int jj = 0; jj < 4; jj++) {
                    const int j = (g & 1) * 4 + jj;
                    const int r = warp_m * 32 + t * 16 + g4;
                    const int cl = jj * 8 + tg * 2;
                    Cs[r * 33 + cl] = acc[t][j][0];
                    Cs[r * 33 + cl + 1] = acc[t][j][1];
                    Cs[(r + 8) * 33 + cl] = acc[t][j][2];
                    Cs[(r + 8) * 33 + cl + 1] = acc[t][j][3];
                }
        }
        __syncthreads();
#pragma unroll
        for (int q = 0; q < 8; q++) {
            const int e = q * 512 + tid;
            const int col = e >> 7, mm = e & 127;
            const int oc = g * 32 + col;
            Ob[(size_t)oc * HWS + mm] = Cs[mm * 33 + col] + sbias[oc];
        }
        __syncthreads();
    }
}

// ---------------- launch ----------------
extern "C" void kernel_launch(void* const* d_in, const int* in_sizes, int n_in,
                              void* d_out, int out_size) {
    (void)in_sizes; (void)n_in; (void)out_size;
    const float* x      = (const float*)d_in[0];
    const float* conv_w = (const float*)d_in[1];
    const float* conv_b = (const float*)d_in[2];
    const float* off_w  = (const float*)d_in[3];
    const float* off_b  = (const float*)d_in[4];
    const float* wgt_w  = (const float*)d_in[5];
    const float* wgt_b  = (const float*)d_in[6];
    const float* gamma  = (const float*)d_in[7];
    const float* beta   = (const float*)d_in[8];
    const float* rmean  = (const float*)d_in[9];
    const float* rvar   = (const float*)d_in[10];
    const float* out_w  = (const float*)d_in[11];
    const float* out_b  = (const float*)d_in[12];
    float* out = (float*)d_out;

    static bool attr_done = false;
    if (!attr_done) {
        cudaFuncSetAttribute(gemm1_mma, cudaFuncAttributeMaxDynamicSharedMemorySize, GEMM_SMEM);
        cudaFuncSetAttribute(gemm2_fused, cudaFuncAttributeMaxDynamicSharedMemorySize, GEMM2_SMEM);
        attr_done = true;
    }

    prep_kernel<<<C, C>>>(conv_w, out_w, out_b, gamma, beta, rmean, rvar);
    gemm1_mma<<<dim3(HWS / 128, C / 128, BATCH), 256, GEMM_SMEM>>>(
        x, conv_b, off_w, off_b, wgt_w, wgt_b);
    gemm2_fused<<<dim3(HWS / 128, BATCH), 512, GEMM2_SMEM>>>(out);
}

// round 13
// speedup vs baseline: 1.0264x; 1.0264x over previous
#include <cuda_runtime.h>
#include <cuda_fp16.h>
#include <cstdint>

// Problem constants
#define BATCH 8
#define C 256
#define KB 4
#define HH 128
#define WW 128
#define HWS 16384
#define NPX (BATCH*HWS)

// ---------------- device scratch ----------------
__device__ __align__(16) __half g_Y[(size_t)NPX * C];   // Y = W2f*proj, fp16 [b][p][o]
__device__ __align__(16) __half g_wc[C * C];            // composed Wc = W2f*W1, fp16 [o][c]
__device__ float g_bcY[C];                              // composed bias for Y
__device__ float g_bias2[C];                            // final bias
__device__ float4 g_cw[(size_t)BATCH * KB * HWS];
__device__ int4   g_idx[(size_t)BATCH * KB * HWS];

// ---------------- helpers ----------------
__device__ __forceinline__ uint32_t smem_u32(const void* p) {
    uint32_t a;
    asm("{ .reg .u64 t; cvta.to.shared.u64 t, %1; cvt.u32.u64 %0, t; }" : "=r"(a) : "l"(p));
    return a;
}

__device__ __forceinline__ void ldsm4(uint32_t* r, uint32_t addr) {
    asm volatile("ldmatrix.sync.aligned.m8n8.x4.shared.b16 {%0,%1,%2,%3}, [%4];"
                 : "=r"(r[0]), "=r"(r[1]), "=r"(r[2]), "=r"(r[3]) : "r"(addr));
}

__device__ __forceinline__ void mma_fp16(float* d, const uint32_t* a, uint32_t b0, uint32_t b1) {
    asm volatile(
        "mma.sync.aligned.m16n8k16.row.col.f32.f16.f16.f32 "
        "{%0,%1,%2,%3}, {%4,%5,%6,%7}, {%8,%9}, {%0,%1,%2,%3};"
        : "+f"(d[0]), "+f"(d[1]), "+f"(d[2]), "+f"(d[3])
        : "r"(a[0]), "r"(a[1]), "r"(a[2]), "r"(a[3]), "r"(b0), "r"(b1));
}

// ============ GEMM (Y): tile 128x128, BK=32, 256 thr, 2 CTA/SM ============
#define ROWB 80
#define TSZ  (128 * ROWB)
#define BUFSZ (2 * TSZ)
#define OFF_A  0
#define OFF_B  TSZ
#define OFF_BIAS (2 * BUFSZ)
#define GEMM_SMEM (OFF_BIAS + 1024)

// ============ sample_out: 128 px x 256 ch f32 tile in smem ============
#define SP_PITCH 264                       // f32 pitch, 1056B (16B-aligned)
#define SAMPLE_SMEM (128 * SP_PITCH * 4)   // 135168

// ---------------- prep: fold BN, compose Wc = W2f * W1, biases ----------------
__global__ void prep_kernel(const float* __restrict__ conv_w, const float* __restrict__ conv_b,
                            const float* __restrict__ out_w, const float* __restrict__ out_b,
                            const float* __restrict__ gamma, const float* __restrict__ beta,
                            const float* __restrict__ rmean, const float* __restrict__ rvar) {
    const int o = blockIdx.x;
    const int c = threadIdx.x;
    __shared__ float w2row[C];
    __shared__ float red[C];

    float inv = gamma[c] / sqrtf(rvar[c] + 1e-5f);
    float w = out_w[o * C + c];
    float w2f = w * inv;
    w2row[c] = w2f;
    red[c] = w * (beta[c] - rmean[c] * inv);
    __syncthreads();

    // bias2[o] = sum_c out_w[o][c]*(beta - rm*inv) + out_b[o]
    for (int s = 128; s > 0; s >>= 1) {
        if (c < s) red[c] += red[c + s];
        __syncthreads();
    }
    if (c == 0) g_bias2[o] = red[0] + out_b[o];
    __syncthreads();

    // bcY[o] = sum_c w2f[o][c]*conv_b[c]
    red[c] = w2row[c] * conv_b[c];
    __syncthreads();
    for (int s = 128; s > 0; s >>= 1) {
        if (c < s) red[c] += red[c + s];
        __syncthreads();
    }
    if (c == 0) g_bcY[o] = red[0];

    // Wc[o][d] = sum_m w2f[o][m] * conv_w[m][d]   (thread = d)
    float acc = 0.f;
#pragma unroll 4
    for (int m = 0; m < C; m++)
        acc = fmaf(w2row[m], conv_w[m * C + c], acc);
    g_wc[o * C + c] = __float2half_rn(acc);
}

// ---------------- GEMM: Y[b][p][o] = x^T @ Wc^T + bcY ----------------
struct PF1 {
    uint32_t a[8];
    int4 b[2];
};

__device__ __forceinline__ void pf1_load(PF1& f, const float* __restrict__ xb,
                                         const __half* __restrict__ w,
                                         int kc, int am, int ach, int tid) {
#pragma unroll
    for (int i = 0; i < 8; i++) {
        int cl = ach * 16 + i * 2;
        float v0 = xb[(size_t)(kc + cl) * HWS + am];
        float v1 = xb[(size_t)(kc + cl + 1) * HWS + am];
        __half2 h = __floats2half2_rn(v0, v1);
        f.a[i] = *reinterpret_cast<uint32_t*>(&h);
    }
#pragma unroll
    for (int j = 0; j < 2; j++) {
        int e = j * 256 + tid;
        int row = e >> 2, ch = e & 3;
        f.b[j] = *(const int4*)(w + (size_t)row * C + kc + ch * 8);
    }
}

__device__ __forceinline__ void pf1_store(const PF1& f, char* base, int am, int ach, int tid) {
#pragma unroll
    for (int i = 0; i < 8; i++) {
        int cl = ach * 16 + i * 2;
        *(uint32_t*)(base + OFF_A + am * ROWB + cl * 2) = f.a[i];
    }
#pragma unroll
    for (int j = 0; j < 2; j++) {
        int e = j * 256 + tid;
        int row = e >> 2, ch = e & 3;
        *(int4*)(base + OFF_B + row * ROWB + ch * 16) = f.b[j];
    }
}

__global__ __launch_bounds__(256) void gemm1_mma(const float* __restrict__ x) {
    extern __shared__ char sm[];
    const uint32_t smb = smem_u32(sm);
    const int tid = threadIdx.x;
    const int wid = tid >> 5, lane = tid & 31;
    const int warp_m = wid & 3, warp_n = wid >> 2;
    const int lr = lane & 15, lc = lane >> 4;
    const int p0 = blockIdx.x * 128, o0 = blockIdx.y * 128, b = blockIdx.z;

    if (tid < 128) ((float*)(sm + OFF_BIAS))[tid] = g_bcY[o0 + tid];

    const float* xb = x + (size_t)b * C * HWS + p0;
    const __half* w = g_wc + (size_t)o0 * C;
    const int am = tid & 127, ach = tid >> 7;

    float acc[2][8][4];
#pragma unroll
    for (int t = 0; t < 2; t++)
#pragma unroll
        for (int j = 0; j < 8; j++)
#pragma unroll
            for (int q = 0; q < 4; q++) acc[t][j][q] = 0.f;

    PF1 f;
    pf1_load(f, xb, w, 0, am, ach, tid);
    pf1_store(f, sm, am, ach, tid);
    __syncthreads();

    for (int kt = 0; kt < 8; kt++) {
        const int buf = kt & 1;
        if (kt < 7) pf1_load(f, xb, w, (kt + 1) * 32, am, ach, tid);
        {
            const uint32_t smbuf = smb + buf * BUFSZ;
            const uint32_t a_base = smbuf + OFF_A + (uint32_t)(warp_m * 32 + lr) * ROWB + lc * 16;
            const uint32_t b_base = smbuf + OFF_B + (uint32_t)(warp_n * 64 + lr) * ROWB + lc * 16;
#pragma unroll
            for (int s = 0; s < 2; s++) {
                uint32_t a[2][4], bb[4][4];
#pragma unroll
                for (int t = 0; t < 2; t++)
                    ldsm4(a[t], a_base + t * (16 * ROWB) + s * 32);
#pragma unroll
                for (int u = 0; u < 4; u++)
                    ldsm4(bb[u], b_base + u * (16 * ROWB) + s * 32);
#pragma unroll
                for (int t = 0; t < 2; t++)
#pragma unroll
                    for (int u = 0; u < 4; u++) {
                        mma_fp16(acc[t][u * 2], a[t], bb[u][0], bb[u][2]);
                        mma_fp16(acc[t][u * 2 + 1], a[t], bb[u][1], bb[u][3]);
                    }
            }
        }
        if (kt < 7) {
            pf1_store(f, sm + (buf ^ 1) * BUFSZ, am, ach, tid);
            __syncthreads();
        }
    }

    // epilogue: write Y fp16 [b][p][o] + bcY
    const float* sbias = (const float*)(sm + OFF_BIAS);
    __half* Cb = g_Y + ((size_t)b * HWS + p0) * C + o0;
    const int g4 = lane >> 2, tg = lane & 3;
#pragma unroll
    for (int t = 0; t < 2; t++) {
        const int r0 = warp_m * 32 + t * 16 + g4;
#pragma unroll
        for (int j = 0; j < 8; j++) {
            const int oc = warp_n * 64 + j * 8 + tg * 2;
            float b0 = sbias[oc], b1 = sbias[oc + 1];
            __half2 v0 = __floats2half2_rn(acc[t][j][0] + b0, acc[t][j][1] + b1);
            __half2 v1 = __floats2half2_rn(acc[t][j][2] + b0, acc[t][j][3] + b1);
            *(uint32_t*)(Cb + (size_t)r0 * C + oc) = *reinterpret_cast<uint32_t*>(&v0);
            *(uint32_t*)(Cb + (size_t)(r0 + 8) * C + oc) = *reinterpret_cast<uint32_t*>(&v1);
        }
    }
}

// ---------------- aux: direct-global GEMV, 1 px/thread ----------------
__global__ __launch_bounds__(256) void aux_kernel(
        const float* __restrict__ x,
        const float* __restrict__ off_w, const float* __restrict__ off_b,
        const float* __restrict__ wgt_w, const float* __restrict__ wgt_b) {
    __shared__ float wsi[C * 12];
    const int tid = threadIdx.x;
    const int pp = blockIdx.x * 256 + tid;
    const int b = pp >> 14;
    const int p = pp & 16383;

    for (int e = tid; e < 2 * C * KB; e += 256) {
        int kd = e >> 8, c = e & 255;
        wsi[c * 12 + kd] = off_w[e];
    }
    for (int e = tid; e < C * KB; e += 256) {
        int k = e >> 8, c = e & 255;
        wsi[c * 12 + 8 + k] = wgt_w[e];
    }
    __syncthreads();

    float acc[12];
#pragma unroll
    for (int j = 0; j < 12; j++) acc[j] = 0.f;

    const float* xb = x + (size_t)b * C * HWS + p;
#pragma unroll 4
    for (int c = 0; c < C; c++) {
        float xv = xb[(size_t)c * HWS];
        const float4* wp = (const float4*)(wsi + c * 12);
        float4 wa = wp[0], wb = wp[1], wc = wp[2];
        acc[0] = fmaf(xv, wa.x, acc[0]);  acc[1] = fmaf(xv, wa.y, acc[1]);
        acc[2] = fmaf(xv, wa.z, acc[2]);  acc[3] = fmaf(xv, wa.w, acc[3]);
        acc[4] = fmaf(xv, wb.x, acc[4]);  acc[5] = fmaf(xv, wb.y, acc[5]);
        acc[6] = fmaf(xv, wb.z, acc[6]);  acc[7] = fmaf(xv, wb.w, acc[7]);
        acc[8] = fmaf(xv, wc.x, acc[8]);  acc[9] = fmaf(xv, wc.y, acc[9]);
        acc[10] = fmaf(xv, wc.z, acc[10]); acc[11] = fmaf(xv, wc.w, acc[11]);
    }

    const int py = p >> 7, px = p & 127;
    float l0 = acc[8] + wgt_b[0], l1 = acc[9] + wgt_b[1];
    float l2 = acc[10] + wgt_b[2], l3 = acc[11] + wgt_b[3];
    float mx = fmaxf(fmaxf(l0, l1), fmaxf(l2, l3));
    float e0 = __expf(l0 - mx), e1 = __expf(l1 - mx);
    float e2 = __expf(l2 - mx), e3 = __expf(l3 - mx);
    float invs = 1.f / (e0 + e1 + e2 + e3);
    float wk4[4] = {e0 * invs, e1 * invs, e2 * invs, e3 * invs};
#pragma unroll
    for (int k = 0; k < KB; k++) {
        float vx = (float)px + acc[2 * k] + off_b[2 * k];
        float vy = (float)py + acc[2 * k + 1] + off_b[2 * k + 1];
        float x0f = floorf(vx), y0f = floorf(vy);
        float wx1 = vx - x0f, wy1 = vy - y0f;
        int x0 = (int)x0f, y0 = (int)y0f;
        bool vx0 = (x0 >= 0) && (x0 <= WW - 1);
        bool vx1 = (x0 + 1 >= 0) && (x0 + 1 <= WW - 1);
        bool vy0 = (y0 >= 0) && (y0 <= HH - 1);
        bool vy1 = (y0 + 1 >= 0) && (y0 + 1 <= HH - 1);
        float wk = wk4[k];
        float w00 = (1.f - wx1) * (1.f - wy1) * wk * (float)(vx0 && vy0);
        float w01 = wx1 * (1.f - wy1) * wk * (float)(vx1 && vy0);
        float w10 = (1.f - wx1) * wy1 * wk * (float)(vx0 && vy1);
        float w11 = wx1 * wy1 * wk * (float)(vx1 && vy1);
        int xc0 = min(max(x0, 0), WW - 1);
        int xc1 = min(max(x0 + 1, 0), WW - 1);
        int yc0 = min(max(y0, 0), HH - 1);
        int yc1 = min(max(y0 + 1, 0), HH - 1);
        size_t off = ((size_t)(b * KB + k)) * HWS + p;
        g_idx[off] = make_int4(yc0 * WW + xc0, yc0 * WW + xc1,
                               yc1 * WW + xc0, yc1 * WW + xc1);
        g_cw[off] = make_float4(w00, w01, w10, w11);
    }
}

// ---------------- sample_out: out[b][o][p] = Y[p] + sum w*Y[idx] + bias2 ----------------
__device__ __forceinline__ void acc_row(float* acc, uint4 v, float w) {
    const __half2* h = reinterpret_cast<const __half2*>(&v);
#pragma unroll
    for (int i = 0; i < 4; i++) {
        float2 f = __half22float2(h[i]);
        acc[2 * i]     = fmaf(w, f.x, acc[2 * i]);
        acc[2 * i + 1] = fmaf(w, f.y, acc[2 * i + 1]);
    }
}

__global__ __launch_bounds__(512) void sample_out(float* __restrict__ out) {
    extern __shared__ float smf[];
    const int tid = threadIdx.x;
    const int wid = tid >> 5, lane = tid & 31;
    const int p0 = blockIdx.x * 128, b = blockIdx.y;

    // ---- gather phase: out-tile [128 px][256 ch] f32 into smem ----
    const uint4* Yb = (const uint4*)g_Y + (size_t)b * HWS * 32;
#pragma unroll
    for (int i = 0; i < 8; i++) {
        const int px = wid * 8 + i;
        const int p = p0 + px;
        const size_t kb = (size_t)b * KB * HWS + p;

        int4 id[KB];
        float4 w[KB];
#pragma unroll
        for (int k = 0; k < KB; k++) {
            id[k] = g_idx[kb + (size_t)k * HWS];
            w[k] = g_cw[kb + (size_t)k * HWS];
        }
        uint4 sv = Yb[(size_t)p * 32 + lane];
        uint4 cv[KB * 4];
#pragma unroll
        for (int k = 0; k < KB; k++) {
            cv[k * 4 + 0] = Yb[(size_t)id[k].x * 32 + lane];
            cv[k * 4 + 1] = Yb[(size_t)id[k].y * 32 + lane];
            cv[k * 4 + 2] = Yb[(size_t)id[k].z * 32 + lane];
            cv[k * 4 + 3] = Yb[(size_t)id[k].w * 32 + lane];
        }
        float acc[8];
        {
            const __half2* h = reinterpret_cast<const __half2*>(&sv);
#pragma unroll
            for (int q = 0; q < 4; q++) {
                float2 f = __half22float2(h[q]);
                acc[2 * q] = f.x;
                acc[2 * q + 1] = f.y;
            }
        }
#pragma unroll
        for (int k = 0; k < KB; k++) {
            acc_row(acc, cv[k * 4 + 0], w[k].x);
            acc_row(acc, cv[k * 4 + 1], w[k].y);
            acc_row(acc, cv[k * 4 + 2], w[k].z);
            acc_row(acc, cv[k * 4 + 3], w[k].w);
        }
        // STS.128 x2, conflict-free (consecutive within px row)
        float* dst = smf + px * SP_PITCH + lane * 8;
        *(float4*)dst = make_float4(acc[0], acc[1], acc[2], acc[3]);
        *(float4*)(dst + 4) = make_float4(acc[4], acc[5], acc[6], acc[7]);
    }
    __syncthreads();

    // ---- epilogue: transpose read (LDS.128) -> coalesced channel-major STG ----
    float* Ob = out + (size_t)b * C * HWS + p0;
    const float4* bias4 = (const float4*)g_bias2;
#pragma unroll
    for (int q = 0; q < 16; q++) {
        const int e = q * 512 + tid;
        const int colg = e >> 7;          // 0..63 (4-channel group)
        const int mm = e & 127;
        float4 v = *(const float4*)(smf + mm * SP_PITCH + colg * 4);
        float4 bi = __ldg(bias4 + colg);
        Ob[(size_t)(colg * 4 + 0) * HWS + mm] = v.x + bi.x;
        Ob[(size_t)(colg * 4 + 1) * HWS + mm] = v.y + bi.y;
        Ob[(size_t)(colg * 4 + 2) * HWS + mm] = v.z + bi.z;
        Ob[(size_t)(colg * 4 + 3) * HWS + mm] = v.w + bi.w;
    }
}

// ---------------- launch ----------------
extern "C" void kernel_launch(void* const* d_in, const int* in_sizes, int n_in,
                              void* d_out, int out_size) {
    (void)in_sizes; (void)n_in; (void)out_size;
    const float* x      = (const float*)d_in[0];
    const float* conv_w = (const float*)d_in[1];
    const float* conv_b = (const float*)d_in[2];
    const float* off_w  = (const float*)d_in[3];
    const float* off_b  = (const float*)d_in[4];
    const float* wgt_w  = (const float*)d_in[5];
    const float* wgt_b  = (const float*)d_in[6];
    const float* gamma  = (const float*)d_in[7];
    const float* beta   = (const float*)d_in[8];
    const float* rmean  = (const float*)d_in[9];
    const float* rvar   = (const float*)d_in[10];
    const float* out_w  = (const float*)d_in[11];
    const float* out_b  = (const float*)d_in[12];
    float* out = (float*)d_out;

    static bool attr_done = false;
    if (!attr_done) {
        cudaFuncSetAttribute(gemm1_mma, cudaFuncAttributeMaxDynamicSharedMemorySize, GEMM_SMEM);
        cudaFuncSetAttribute(sample_out, cudaFuncAttributeMaxDynamicSharedMemorySize, SAMPLE_SMEM);
        attr_done = true;
    }

    prep_kernel<<<C, C>>>(conv_w, conv_b, out_w, out_b, gamma, beta, rmean, rvar);
    gemm1_mma<<<dim3(HWS / 128, C / 128, BATCH), 256, GEMM_SMEM>>>(x);
    aux_kernel<<<NPX / 256, 256>>>(x, off_w, off_b, wgt_w, wgt_b);
    sample_out<<<dim3(HWS / 128, BATCH), 512, SAMPLE_SMEM>>>(out);
}

// round 14
// speedup vs baseline: 1.1247x; 1.0958x over previous
#include <cuda_runtime.h>
#include <cuda_fp16.h>
#include <cstdint>

// Problem constants
#define BATCH 8
#define C 256
#define KB 4
#define HH 128
#define WW 128
#define HWS 16384
#define NPX (BATCH*HWS)

// ---------------- device scratch ----------------
__device__ __align__(16) __half g_Y[(size_t)NPX * C];   // Y = W2f*proj, fp16 [b][p][o]
__device__ __align__(16) __half g_wc[C * C];            // composed Wc = W2f*W1, fp16 [o][c]
__device__ float g_bcY[C];                              // composed bias for Y
__device__ float g_bias2[C];                            // final bias
__device__ float4 g_cw[(size_t)BATCH * KB * HWS];
__device__ int4   g_idx[(size_t)BATCH * KB * HWS];

// ---------------- helpers ----------------
__device__ __forceinline__ uint32_t smem_u32(const void* p) {
    uint32_t a;
    asm("{ .reg .u64 t; cvta.to.shared.u64 t, %1; cvt.u32.u64 %0, t; }" : "=r"(a) : "l"(p));
    return a;
}

__device__ __forceinline__ void ldsm4(uint32_t* r, uint32_t addr) {
    asm volatile("ldmatrix.sync.aligned.m8n8.x4.shared.b16 {%0,%1,%2,%3}, [%4];"
                 : "=r"(r[0]), "=r"(r[1]), "=r"(r[2]), "=r"(r[3]) : "r"(addr));
}

__device__ __forceinline__ void mma_fp16(float* d, const uint32_t* a, uint32_t b0, uint32_t b1) {
    asm volatile(
        "mma.sync.aligned.m16n8k16.row.col.f32.f16.f16.f32 "
        "{%0,%1,%2,%3}, {%4,%5,%6,%7}, {%8,%9}, {%0,%1,%2,%3};"
        : "+f"(d[0]), "+f"(d[1]), "+f"(d[2]), "+f"(d[3])
        : "r"(a[0]), "r"(a[1]), "r"(a[2]), "r"(a[3]), "r"(b0), "r"(b1));
}

// ============ GEMM (Y): tile 128x128, BK=32, 256 thr, 2 CTA/SM ============
#define ROWB 80
#define TSZ  (128 * ROWB)
#define BUFSZ (2 * TSZ)
#define OFF_A  0
#define OFF_B  TSZ
#define OFF_BIAS (2 * BUFSZ)
#define GEMM_SMEM (OFF_BIAS + 1024)

// ============ sample_out: 64 px x 256 ch f32 tile, 256 thr, 3 CTA/SM ============
#define SPX 64
#define SP_PITCH 264                        // f32 pitch (1056B)
#define SAMPLE_SMEM (SPX * SP_PITCH * 4)    // 67584

// ---------------- prep: fold BN, compose Wc = W2f * W1, biases ----------------
__global__ void prep_kernel(const float* __restrict__ conv_w, const float* __restrict__ conv_b,
                            const float* __restrict__ out_w, const float* __restrict__ out_b,
                            const float* __restrict__ gamma, const float* __restrict__ beta,
                            const float* __restrict__ rmean, const float* __restrict__ rvar) {
    const int o = blockIdx.x;
    const int c = threadIdx.x;
    __shared__ float w2row[C];
    __shared__ float red[C];

    float inv = gamma[c] / sqrtf(rvar[c] + 1e-5f);
    float w = out_w[o * C + c];
    float w2f = w * inv;
    w2row[c] = w2f;
    red[c] = w * (beta[c] - rmean[c] * inv);
    __syncthreads();

    for (int s = 128; s > 0; s >>= 1) {
        if (c < s) red[c] += red[c + s];
        __syncthreads();
    }
    if (c == 0) g_bias2[o] = red[0] + out_b[o];
    __syncthreads();

    red[c] = w2row[c] * conv_b[c];
    __syncthreads();
    for (int s = 128; s > 0; s >>= 1) {
        if (c < s) red[c] += red[c + s];
        __syncthreads();
    }
    if (c == 0) g_bcY[o] = red[0];

    float acc = 0.f;
#pragma unroll 4
    for (int m = 0; m < C; m++)
        acc = fmaf(w2row[m], conv_w[m * C + c], acc);
    g_wc[o * C + c] = __float2half_rn(acc);
}

// ---------------- GEMM: Y[b][p][o] = x^T @ Wc^T + bcY ----------------
struct PF1 {
    uint32_t a[8];
    int4 b[2];
};

__device__ __forceinline__ void pf1_load(PF1& f, const float* __restrict__ xb,
                                         const __half* __restrict__ w,
                                         int kc, int am, int ach, int tid) {
#pragma unroll
    for (int i = 0; i < 8; i++) {
        int cl = ach * 16 + i * 2;
        float v0 = xb[(size_t)(kc + cl) * HWS + am];
        float v1 = xb[(size_t)(kc + cl + 1) * HWS + am];
        __half2 h = __floats2half2_rn(v0, v1);
        f.a[i] = *reinterpret_cast<uint32_t*>(&h);
    }
#pragma unroll
    for (int j = 0; j < 2; j++) {
        int e = j * 256 + tid;
        int row = e >> 2, ch = e & 3;
        f.b[j] = *(const int4*)(w + (size_t)row * C + kc + ch * 8);
    }
}

__device__ __forceinline__ void pf1_store(const PF1& f, char* base, int am, int ach, int tid) {
#pragma unroll
    for (int i = 0; i < 8; i++) {
        int cl = ach * 16 + i * 2;
        *(uint32_t*)(base + OFF_A + am * ROWB + cl * 2) = f.a[i];
    }
#pragma unroll
    for (int j = 0; j < 2; j++) {
        int e = j * 256 + tid;
        int row = e >> 2, ch = e & 3;
        *(int4*)(base + OFF_B + row * ROWB + ch * 16) = f.b[j];
    }
}

__global__ __launch_bounds__(256) void gemm1_mma(const float* __restrict__ x) {
    extern __shared__ char sm[];
    const uint32_t smb = smem_u32(sm);
    const int tid = threadIdx.x;
    const int wid = tid >> 5, lane = tid & 31;
    const int warp_m = wid & 3, warp_n = wid >> 2;
    const int lr = lane & 15, lc = lane >> 4;
    const int p0 = blockIdx.x * 128, o0 = blockIdx.y * 128, b = blockIdx.z;

    if (tid < 128) ((float*)(sm + OFF_BIAS))[tid] = g_bcY[o0 + tid];

    const float* xb = x + (size_t)b * C * HWS + p0;
    const __half* w = g_wc + (size_t)o0 * C;
    const int am = tid & 127, ach = tid >> 7;

    float acc[2][8][4];
#pragma unroll
    for (int t = 0; t < 2; t++)
#pragma unroll
        for (int j = 0; j < 8; j++)
#pragma unroll
            for (int q = 0; q < 4; q++) acc[t][j][q] = 0.f;

    PF1 f;
    pf1_load(f, xb, w, 0, am, ach, tid);
    pf1_store(f, sm, am, ach, tid);
    __syncthreads();

    for (int kt = 0; kt < 8; kt++) {
        const int buf = kt & 1;
        if (kt < 7) pf1_load(f, xb, w, (kt + 1) * 32, am, ach, tid);
        {
            const uint32_t smbuf = smb + buf * BUFSZ;
            const uint32_t a_base = smbuf + OFF_A + (uint32_t)(warp_m * 32 + lr) * ROWB + lc * 16;
            const uint32_t b_base = smbuf + OFF_B + (uint32_t)(warp_n * 64 + lr) * ROWB + lc * 16;
#pragma unroll
            for (int s = 0; s < 2; s++) {
                uint32_t a[2][4], bb[4][4];
#pragma unroll
                for (int t = 0; t < 2; t++)
                    ldsm4(a[t], a_base + t * (16 * ROWB) + s * 32);
#pragma unroll
                for (int u = 0; u < 4; u++)
                    ldsm4(bb[u], b_base + u * (16 * ROWB) + s * 32);
#pragma unroll
                for (int t = 0; t < 2; t++)
#pragma unroll
                    for (int u = 0; u < 4; u++) {
                        mma_fp16(acc[t][u * 2], a[t], bb[u][0], bb[u][2]);
                        mma_fp16(acc[t][u * 2 + 1], a[t], bb[u][1], bb[u][3]);
                    }
            }
        }
        if (kt < 7) {
            pf1_store(f, sm + (buf ^ 1) * BUFSZ, am, ach, tid);
            __syncthreads();
        }
    }

    // epilogue: write Y fp16 [b][p][o] + bcY
    const float* sbias = (const float*)(sm + OFF_BIAS);
    __half* Cb = g_Y + ((size_t)b * HWS + p0) * C + o0;
    const int g4 = lane >> 2, tg = lane & 3;
#pragma unroll
    for (int t = 0; t < 2; t++) {
        const int r0 = warp_m * 32 + t * 16 + g4;
#pragma unroll
        for (int j = 0; j < 8; j++) {
            const int oc = warp_n * 64 + j * 8 + tg * 2;
            float b0 = sbias[oc], b1 = sbias[oc + 1];
            __half2 v0 = __floats2half2_rn(acc[t][j][0] + b0, acc[t][j][1] + b1);
            __half2 v1 = __floats2half2_rn(acc[t][j][2] + b0, acc[t][j][3] + b1);
            *(uint32_t*)(Cb + (size_t)r0 * C + oc) = *reinterpret_cast<uint32_t*>(&v0);
            *(uint32_t*)(Cb + (size_t)(r0 + 8) * C + oc) = *reinterpret_cast<uint32_t*>(&v1);
        }
    }
}

// ---------------- aux: direct-global GEMV, 1 px/thread ----------------
__global__ __launch_bounds__(256) void aux_kernel(
        const float* __restrict__ x,
        const float* __restrict__ off_w, const float* __restrict__ off_b,
        const float* __restrict__ wgt_w, const float* __restrict__ wgt_b) {
    __shared__ float wsi[C * 12];
    const int tid = threadIdx.x;
    const int pp = blockIdx.x * 256 + tid;
    const int b = pp >> 14;
    const int p = pp & 16383;

    for (int e = tid; e < 2 * C * KB; e += 256) {
        int kd = e >> 8, c = e & 255;
        wsi[c * 12 + kd] = off_w[e];
    }
    for (int e = tid; e < C * KB; e += 256) {
        int k = e >> 8, c = e & 255;
        wsi[c * 12 + 8 + k] = wgt_w[e];
    }
    __syncthreads();

    float acc[12];
#pragma unroll
    for (int j = 0; j < 12; j++) acc[j] = 0.f;

    const float* xb = x + (size_t)b * C * HWS + p;
#pragma unroll 4
    for (int c = 0; c < C; c++) {
        float xv = xb[(size_t)c * HWS];
        const float4* wp = (const float4*)(wsi + c * 12);
        float4 wa = wp[0], wb = wp[1], wc = wp[2];
        acc[0] = fmaf(xv, wa.x, acc[0]);  acc[1] = fmaf(xv, wa.y, acc[1]);
        acc[2] = fmaf(xv, wa.z, acc[2]);  acc[3] = fmaf(xv, wa.w, acc[3]);
        acc[4] = fmaf(xv, wb.x, acc[4]);  acc[5] = fmaf(xv, wb.y, acc[5]);
        acc[6] = fmaf(xv, wb.z, acc[6]);  acc[7] = fmaf(xv, wb.w, acc[7]);
        acc[8] = fmaf(xv, wc.x, acc[8]);  acc[9] = fmaf(xv, wc.y, acc[9]);
        acc[10] = fmaf(xv, wc.z, acc[10]); acc[11] = fmaf(xv, wc.w, acc[11]);
    }

    const int py = p >> 7, px = p & 127;
    float l0 = acc[8] + wgt_b[0], l1 = acc[9] + wgt_b[1];
    float l2 = acc[10] + wgt_b[2], l3 = acc[11] + wgt_b[3];
    float mx = fmaxf(fmaxf(l0, l1), fmaxf(l2, l3));
    float e0 = __expf(l0 - mx), e1 = __expf(l1 - mx);
    float e2 = __expf(l2 - mx), e3 = __expf(l3 - mx);
    float invs = 1.f / (e0 + e1 + e2 + e3);
    float wk4[4] = {e0 * invs, e1 * invs, e2 * invs, e3 * invs};
#pragma unroll
    for (int k = 0; k < KB; k++) {
        float vx = (float)px + acc[2 * k] + off_b[2 * k];
        float vy = (float)py + acc[2 * k + 1] + off_b[2 * k + 1];
        float x0f = floorf(vx), y0f = floorf(vy);
        float wx1 = vx - x0f, wy1 = vy - y0f;
        int x0 = (int)x0f, y0 = (int)y0f;
        bool vx0 = (x0 >= 0) && (x0 <= WW - 1);
        bool vx1 = (x0 + 1 >= 0) && (x0 + 1 <= WW - 1);
        bool vy0 = (y0 >= 0) && (y0 <= HH - 1);
        bool vy1 = (y0 + 1 >= 0) && (y0 + 1 <= HH - 1);
        float wk = wk4[k];
        float w00 = (1.f - wx1) * (1.f - wy1) * wk * (float)(vx0 && vy0);
        float w01 = wx1 * (1.f - wy1) * wk * (float)(vx1 && vy0);
        float w10 = (1.f - wx1) * wy1 * wk * (float)(vx0 && vy1);
        float w11 = wx1 * wy1 * wk * (float)(vx1 && vy1);
        int xc0 = min(max(x0, 0), WW - 1);
        int xc1 = min(max(x0 + 1, 0), WW - 1);
        int yc0 = min(max(y0, 0), HH - 1);
        int yc1 = min(max(y0 + 1, 0), HH - 1);
        size_t off = ((size_t)(b * KB + k)) * HWS + p;
        g_idx[off] = make_int4(yc0 * WW + xc0, yc0 * WW + xc1,
                               yc1 * WW + xc0, yc1 * WW + xc1);
        g_cw[off] = make_float4(w00, w01, w10, w11);
    }
}

// ---------------- sample_out: out[b][o][p] = Y[p] + sum w*Y[idx] + bias2 ----------------
__device__ __forceinline__ void acc_row(float* acc, uint4 v, float w) {
    const __half2* h = reinterpret_cast<const __half2*>(&v);
#pragma unroll
    for (int i = 0; i < 4; i++) {
        float2 f = __half22float2(h[i]);
        acc[2 * i]     = fmaf(w, f.x, acc[2 * i]);
        acc[2 * i + 1] = fmaf(w, f.y, acc[2 * i + 1]);
    }
}

__global__ __launch_bounds__(256) void sample_out(float* __restrict__ out) {
    extern __shared__ float smf[];
    const int tid = threadIdx.x;
    const int wid = tid >> 5, lane = tid & 31;
    const int p0 = blockIdx.x * SPX, b = blockIdx.y;

    // ---- gather phase: out-tile [64 px][256 ch] f32 into smem ----
    const uint4* Yb = (const uint4*)g_Y + (size_t)b * HWS * 32;
#pragma unroll
    for (int i = 0; i < 8; i++) {
        const int px = wid * 8 + i;
        const int p = p0 + px;
        const size_t kb = (size_t)b * KB * HWS + p;

        int4 id[KB];
        float4 w[KB];
#pragma unroll
        for (int k = 0; k < KB; k++) {
            id[k] = g_idx[kb + (size_t)k * HWS];
            w[k] = g_cw[kb + (size_t)k * HWS];
        }
        uint4 sv = Yb[(size_t)p * 32 + lane];
        uint4 cv[KB * 4];
#pragma unroll
        for (int k = 0; k < KB; k++) {
            cv[k * 4 + 0] = Yb[(size_t)id[k].x * 32 + lane];
            cv[k * 4 + 1] = Yb[(size_t)id[k].y * 32 + lane];
            cv[k * 4 + 2] = Yb[(size_t)id[k].z * 32 + lane];
            cv[k * 4 + 3] = Yb[(size_t)id[k].w * 32 + lane];
        }
        float acc[8];
        {
            const __half2* h = reinterpret_cast<const __half2*>(&sv);
#pragma unroll
            for (int q = 0; q < 4; q++) {
                float2 f = __half22float2(h[q]);
                acc[2 * q] = f.x;
                acc[2 * q + 1] = f.y;
            }
        }
#pragma unroll
        for (int k = 0; k < KB; k++) {
            acc_row(acc, cv[k * 4 + 0], w[k].x);
            acc_row(acc, cv[k * 4 + 1], w[k].y);
            acc_row(acc, cv[k * 4 + 2], w[k].z);
            acc_row(acc, cv[k * 4 + 3], w[k].w);
        }
        float* dst = smf + px * SP_PITCH + lane * 8;
        *(float4*)dst = make_float4(acc[0], acc[1], acc[2], acc[3]);
        *(float4*)(dst + 4) = make_float4(acc[4], acc[5], acc[6], acc[7]);
    }
    __syncthreads();

    // ---- epilogue: transpose read (LDS.128) -> coalesced channel-major STG ----
    float* Ob = out + (size_t)b * C * HWS + p0;
    const float4* bias4 = (const float4*)g_bias2;
#pragma unroll
    for (int q = 0; q < 16; q++) {
        const int e = q * 256 + tid;
        const int colg = e >> 6;          // 0..63 (4-channel group)
        const int mm = e & 63;            // pixel within tile
        float4 v = *(const float4*)(smf + mm * SP_PITCH + colg * 4);
        float4 bi = __ldg(bias4 + colg);
        Ob[(size_t)(colg * 4 + 0) * HWS + mm] = v.x + bi.x;
        Ob[(size_t)(colg * 4 + 1) * HWS + mm] = v.y + bi.y;
        Ob[(size_t)(colg * 4 + 2) * HWS + mm] = v.z + bi.z;
        Ob[(size_t)(colg * 4 + 3) * HWS + mm] = v.w + bi.w;
    }
}

// ---------------- launch ----------------
extern "C" void kernel_launch(void* const* d_in, const int* in_sizes, int n_in,
                              void* d_out, int out_size) {
    (void)in_sizes; (void)n_in; (void)out_size;
    const float* x      = (const float*)d_in[0];
    const float* conv_w = (const float*)d_in[1];
    const float* conv_b = (const float*)d_in[2];
    const float* off_w  = (const float*)d_in[3];
    const float* off_b  = (const float*)d_in[4];
    const float* wgt_w  = (const float*)d_in[5];
    const float* wgt_b  = (const float*)d_in[6];
    const float* gamma  = (const float*)d_in[7];
    const float* beta   = (const float*)d_in[8];
    const float* rmean  = (const float*)d_in[9];
    const float* rvar   = (const float*)d_in[10];
    const float* out_w  = (const float*)d_in[11];
    const float* out_b  = (const float*)d_in[12];
    float* out = (float*)d_out;

    static bool attr_done = false;
    if (!attr_done) {
        cudaFuncSetAttribute(gemm1_mma, cudaFuncAttributeMaxDynamicSharedMemorySize, GEMM_SMEM);
        cudaFuncSetAttribute(sample_out, cudaFuncAttributeMaxDynamicSharedMemorySize, SAMPLE_SMEM);
        attr_done = true;
    }

    prep_kernel<<<C, C>>>(conv_w, conv_b, out_w, out_b, gamma, beta, rmean, rvar);
    gemm1_mma<<<dim3(HWS / 128, C / 128, BATCH), 256, GEMM_SMEM>>>(x);
    aux_kernel<<<NPX / 256, 256>>>(x, off_w, off_b, wgt_w, wgt_b);
    sample_out<<<dim3(HWS / SPX, BATCH), 256, SAMPLE_SMEM>>>(out);
}

// round 15
// speedup vs baseline: 1.2351x; 1.0982x over previous
#include <cuda_runtime.h>
#include <cuda_fp16.h>
#include <cstdint>

// Problem constants
#define BATCH 8
#define C 256
#define KB 4
#define HH 128
#define WW 128
#define HWS 16384
#define NPX (BATCH*HWS)

// ---------------- device scratch ----------------
__device__ __align__(16) __half g_Y[(size_t)NPX * C];   // Y = W2f*proj, fp16 [b][p][o]
__device__ __align__(16) __half g_wc[C * C];            // composed Wc = W2f*W1, fp16 [o][c]
__device__ float g_bcY[C];                              // composed bias for Y
__device__ float g_bias2[C];                            // final bias
__device__ float4 g_cw[(size_t)BATCH * KB * HWS];
__device__ int4   g_idx[(size_t)BATCH * KB * HWS];

// ---------------- helpers ----------------
__device__ __forceinline__ uint32_t smem_u32(const void* p) {
    uint32_t a;
    asm("{ .reg .u64 t; cvta.to.shared.u64 t, %1; cvt.u32.u64 %0, t; }" : "=r"(a) : "l"(p));
    return a;
}

__device__ __forceinline__ void ldsm4(uint32_t* r, uint32_t addr) {
    asm volatile("ldmatrix.sync.aligned.m8n8.x4.shared.b16 {%0,%1,%2,%3}, [%4];"
                 : "=r"(r[0]), "=r"(r[1]), "=r"(r[2]), "=r"(r[3]) : "r"(addr));
}

__device__ __forceinline__ void mma_fp16(float* d, const uint32_t* a, uint32_t b0, uint32_t b1) {
    asm volatile(
        "mma.sync.aligned.m16n8k16.row.col.f32.f16.f16.f32 "
        "{%0,%1,%2,%3}, {%4,%5,%6,%7}, {%8,%9}, {%0,%1,%2,%3};"
        : "+f"(d[0]), "+f"(d[1]), "+f"(d[2]), "+f"(d[3])
        : "r"(a[0]), "r"(a[1]), "r"(a[2]), "r"(a[3]), "r"(b0), "r"(b1));
}

// ============ GEMM (Y): tile 128x128, BK=32, 256 thr, 2 CTA/SM ============
#define ROWB 80
#define TSZ  (128 * ROWB)
#define BUFSZ (2 * TSZ)
#define OFF_A  0
#define OFF_B  TSZ
#define OFF_BIAS (2 * BUFSZ)
#define GEMM_SMEM (OFF_BIAS + 1024)

// ============ sample_out: 64 px x 256 ch fp16 tile, 256 thr, 5 CTA/SM ============
#define SPX 64
#define SP_PITCH 264                        // halves per row (528B, 16B-pad)
#define SAMPLE_SMEM (SPX * SP_PITCH * 2)    // 33792

// ---------------- prep: fold BN, compose Wc = W2f * W1, biases ----------------
__global__ void prep_kernel(const float* __restrict__ conv_w, const float* __restrict__ conv_b,
                            const float* __restrict__ out_w, const float* __restrict__ out_b,
                            const float* __restrict__ gamma, const float* __restrict__ beta,
                            const float* __restrict__ rmean, const float* __restrict__ rvar) {
    const int o = blockIdx.x;
    const int c = threadIdx.x;
    __shared__ float w2row[C];
    __shared__ float red[C];

    float inv = gamma[c] / sqrtf(rvar[c] + 1e-5f);
    float w = out_w[o * C + c];
    float w2f = w * inv;
    w2row[c] = w2f;
    red[c] = w * (beta[c] - rmean[c] * inv);
    __syncthreads();

    for (int s = 128; s > 0; s >>= 1) {
        if (c < s) red[c] += red[c + s];
        __syncthreads();
    }
    if (c == 0) g_bias2[o] = red[0] + out_b[o];
    __syncthreads();

    red[c] = w2row[c] * conv_b[c];
    __syncthreads();
    for (int s = 128; s > 0; s >>= 1) {
        if (c < s) red[c] += red[c + s];
        __syncthreads();
    }
    if (c == 0) g_bcY[o] = red[0];

    float acc = 0.f;
#pragma unroll 4
    for (int m = 0; m < C; m++)
        acc = fmaf(w2row[m], conv_w[m * C + c], acc);
    g_wc[o * C + c] = __float2half_rn(acc);
}

// ---------------- GEMM: Y[b][p][o] = x^T @ Wc^T + bcY ----------------
struct PF1 {
    uint32_t a[8];
    int4 b[2];
};

__device__ __forceinline__ void pf1_load(PF1& f, const float* __restrict__ xb,
                                         const __half* __restrict__ w,
                                         int kc, int am, int ach, int tid) {
#pragma unroll
    for (int i = 0; i < 8; i++) {
        int cl = ach * 16 + i * 2;
        float v0 = xb[(size_t)(kc + cl) * HWS + am];
        float v1 = xb[(size_t)(kc + cl + 1) * HWS + am];
        __half2 h = __floats2half2_rn(v0, v1);
        f.a[i] = *reinterpret_cast<uint32_t*>(&h);
    }
#pragma unroll
    for (int j = 0; j < 2; j++) {
        int e = j * 256 + tid;
        int row = e >> 2, ch = e & 3;
        f.b[j] = *(const int4*)(w + (size_t)row * C + kc + ch * 8);
    }
}

__device__ __forceinline__ void pf1_store(const PF1& f, char* base, int am, int ach, int tid) {
#pragma unroll
    for (int i = 0; i < 8; i++) {
        int cl = ach * 16 + i * 2;
        *(uint32_t*)(base + OFF_A + am * ROWB + cl * 2) = f.a[i];
    }
#pragma unroll
    for (int j = 0; j < 2; j++) {
        int e = j * 256 + tid;
        int row = e >> 2, ch = e & 3;
        *(int4*)(base + OFF_B + row * ROWB + ch * 16) = f.b[j];
    }
}

__global__ __launch_bounds__(256) void gemm1_mma(const float* __restrict__ x) {
    extern __shared__ char sm[];
    const uint32_t smb = smem_u32(sm);
    const int tid = threadIdx.x;
    const int wid = tid >> 5, lane = tid & 31;
    const int warp_m = wid & 3, warp_n = wid >> 2;
    const int lr = lane & 15, lc = lane >> 4;
    const int p0 = blockIdx.x * 128, o0 = blockIdx.y * 128, b = blockIdx.z;

    if (tid < 128) ((float*)(sm + OFF_BIAS))[tid] = g_bcY[o0 + tid];

    const float* xb = x + (size_t)b * C * HWS + p0;
    const __half* w = g_wc + (size_t)o0 * C;
    const int am = tid & 127, ach = tid >> 7;

    float acc[2][8][4];
#pragma unroll
    for (int t = 0; t < 2; t++)
#pragma unroll
        for (int j = 0; j < 8; j++)
#pragma unroll
            for (int q = 0; q < 4; q++) acc[t][j][q] = 0.f;

    PF1 f;
    pf1_load(f, xb, w, 0, am, ach, tid);
    pf1_store(f, sm, am, ach, tid);
    __syncthreads();

    for (int kt = 0; kt < 8; kt++) {
        const int buf = kt & 1;
        if (kt < 7) pf1_load(f, xb, w, (kt + 1) * 32, am, ach, tid);
        {
            const uint32_t smbuf = smb + buf * BUFSZ;
            const uint32_t a_base = smbuf + OFF_A + (uint32_t)(warp_m * 32 + lr) * ROWB + lc * 16;
            const uint32_t b_base = smbuf + OFF_B + (uint32_t)(warp_n * 64 + lr) * ROWB + lc * 16;
#pragma unroll
            for (int s = 0; s < 2; s++) {
                uint32_t a[2][4], bb[4][4];
#pragma unroll
                for (int t = 0; t < 2; t++)
                    ldsm4(a[t], a_base + t * (16 * ROWB) + s * 32);
#pragma unroll
                for (int u = 0; u < 4; u++)
                    ldsm4(bb[u], b_base + u * (16 * ROWB) + s * 32);
#pragma unroll
                for (int t = 0; t < 2; t++)
#pragma unroll
                    for (int u = 0; u < 4; u++) {
                        mma_fp16(acc[t][u * 2], a[t], bb[u][0], bb[u][2]);
                        mma_fp16(acc[t][u * 2 + 1], a[t], bb[u][1], bb[u][3]);
                    }
            }
        }
        if (kt < 7) {
            pf1_store(f, sm + (buf ^ 1) * BUFSZ, am, ach, tid);
            __syncthreads();
        }
    }

    // epilogue: write Y fp16 [b][p][o] + bcY
    const float* sbias = (const float*)(sm + OFF_BIAS);
    __half* Cb = g_Y + ((size_t)b * HWS + p0) * C + o0;
    const int g4 = lane >> 2, tg = lane & 3;
#pragma unroll
    for (int t = 0; t < 2; t++) {
        const int r0 = warp_m * 32 + t * 16 + g4;
#pragma unroll
        for (int j = 0; j < 8; j++) {
            const int oc = warp_n * 64 + j * 8 + tg * 2;
            float b0 = sbias[oc], b1 = sbias[oc + 1];
            __half2 v0 = __floats2half2_rn(acc[t][j][0] + b0, acc[t][j][1] + b1);
            __half2 v1 = __floats2half2_rn(acc[t][j][2] + b0, acc[t][j][3] + b1);
            *(uint32_t*)(Cb + (size_t)r0 * C + oc) = *reinterpret_cast<uint32_t*>(&v0);
            *(uint32_t*)(Cb + (size_t)(r0 + 8) * C + oc) = *reinterpret_cast<uint32_t*>(&v1);
        }
    }
}

// ---------------- aux: direct-global GEMV, 1 px/thread ----------------
__global__ __launch_bounds__(256) void aux_kernel(
        const float* __restrict__ x,
        const float* __restrict__ off_w, const float* __restrict__ off_b,
        const float* __restrict__ wgt_w, const float* __restrict__ wgt_b) {
    __shared__ float wsi[C * 12];
    const int tid = threadIdx.x;
    const int pp = blockIdx.x * 256 + tid;
    const int b = pp >> 14;
    const int p = pp & 16383;

    for (int e = tid; e < 2 * C * KB; e += 256) {
        int kd = e >> 8, c = e & 255;
        wsi[c * 12 + kd] = off_w[e];
    }
    for (int e = tid; e < C * KB; e += 256) {
        int k = e >> 8, c = e & 255;
        wsi[c * 12 + 8 + k] = wgt_w[e];
    }
    __syncthreads();

    float acc[12];
#pragma unroll
    for (int j = 0; j < 12; j++) acc[j] = 0.f;

    const float* xb = x + (size_t)b * C * HWS + p;
#pragma unroll 4
    for (int c = 0; c < C; c++) {
        float xv = xb[(size_t)c * HWS];
        const float4* wp = (const float4*)(wsi + c * 12);
        float4 wa = wp[0], wb = wp[1], wc = wp[2];
        acc[0] = fmaf(xv, wa.x, acc[0]);  acc[1] = fmaf(xv, wa.y, acc[1]);
        acc[2] = fmaf(xv, wa.z, acc[2]);  acc[3] = fmaf(xv, wa.w, acc[3]);
        acc[4] = fmaf(xv, wb.x, acc[4]);  acc[5] = fmaf(xv, wb.y, acc[5]);
        acc[6] = fmaf(xv, wb.z, acc[6]);  acc[7] = fmaf(xv, wb.w, acc[7]);
        acc[8] = fmaf(xv, wc.x, acc[8]);  acc[9] = fmaf(xv, wc.y, acc[9]);
        acc[10] = fmaf(xv, wc.z, acc[10]); acc[11] = fmaf(xv, wc.w, acc[11]);
    }

    const int py = p >> 7, px = p & 127;
    float l0 = acc[8] + wgt_b[0], l1 = acc[9] + wgt_b[1];
    float l2 = acc[10] + wgt_b[2], l3 = acc[11] + wgt_b[3];
    float mx = fmaxf(fmaxf(l0, l1), fmaxf(l2, l3));
    float e0 = __expf(l0 - mx), e1 = __expf(l1 - mx);
    float e2 = __expf(l2 - mx), e3 = __expf(l3 - mx);
    float invs = 1.f / (e0 + e1 + e2 + e3);
    float wk4[4] = {e0 * invs, e1 * invs, e2 * invs, e3 * invs};
#pragma unroll
    for (int k = 0; k < KB; k++) {
        float vx = (float)px + acc[2 * k] + off_b[2 * k];
        float vy = (float)py + acc[2 * k + 1] + off_b[2 * k + 1];
        float x0f = floorf(vx), y0f = floorf(vy);
        float wx1 = vx - x0f, wy1 = vy - y0f;
        int x0 = (int)x0f, y0 = (int)y0f;
        bool vx0 = (x0 >= 0) && (x0 <= WW - 1);
        bool vx1 = (x0 + 1 >= 0) && (x0 + 1 <= WW - 1);
        bool vy0 = (y0 >= 0) && (y0 <= HH - 1);
        bool vy1 = (y0 + 1 >= 0) && (y0 + 1 <= HH - 1);
        float wk = wk4[k];
        float w00 = (1.f - wx1) * (1.f - wy1) * wk * (float)(vx0 && vy0);
        float w01 = wx1 * (1.f - wy1) * wk * (float)(vx1 && vy0);
        float w10 = (1.f - wx1) * wy1 * wk * (float)(vx0 && vy1);
        float w11 = wx1 * wy1 * wk * (float)(vx1 && vy1);
        int xc0 = min(max(x0, 0), WW - 1);
        int xc1 = min(max(x0 + 1, 0), WW - 1);
        int yc0 = min(max(y0, 0), HH - 1);
        int yc1 = min(max(y0 + 1, 0), HH - 1);
        size_t off = ((size_t)(b * KB + k)) * HWS + p;
        g_idx[off] = make_int4(yc0 * WW + xc0, yc0 * WW + xc1,
                               yc1 * WW + xc0, yc1 * WW + xc1);
        g_cw[off] = make_float4(w00, w01, w10, w11);
    }
}

// ---------------- sample_out: out[b][o][p] = Y[p] + sum w*Y[idx] + bias2 ----------------
__device__ __forceinline__ void acc_row(float* acc, uint4 v, float w) {
    const __half2* h = reinterpret_cast<const __half2*>(&v);
#pragma unroll
    for (int i = 0; i < 4; i++) {
        float2 f = __half22float2(h[i]);
        acc[2 * i]     = fmaf(w, f.x, acc[2 * i]);
        acc[2 * i + 1] = fmaf(w, f.y, acc[2 * i + 1]);
    }
}

__global__ __launch_bounds__(256) void sample_out(float* __restrict__ out) {
    extern __shared__ __half smh[];
    const int tid = threadIdx.x;
    const int wid = tid >> 5, lane = tid & 31;
    const int p0 = blockIdx.x * SPX, b = blockIdx.y;

    // ---- gather phase: out-tile [64 px][256 ch] fp16 into smem ----
    const uint4* Yb = (const uint4*)g_Y + (size_t)b * HWS * 32;
#pragma unroll
    for (int i = 0; i < 8; i++) {
        const int px = wid * 8 + i;
        const int p = p0 + px;
        const size_t kb = (size_t)b * KB * HWS + p;

        int4 id[KB];
        float4 w[KB];
#pragma unroll
        for (int k = 0; k < KB; k++) {
            id[k] = g_idx[kb + (size_t)k * HWS];
            w[k] = g_cw[kb + (size_t)k * HWS];
        }
        uint4 sv = Yb[(size_t)p * 32 + lane];
        uint4 cv[KB * 4];
#pragma unroll
        for (int k = 0; k < KB; k++) {
            cv[k * 4 + 0] = Yb[(size_t)id[k].x * 32 + lane];
            cv[k * 4 + 1] = Yb[(size_t)id[k].y * 32 + lane];
            cv[k * 4 + 2] = Yb[(size_t)id[k].z * 32 + lane];
            cv[k * 4 + 3] = Yb[(size_t)id[k].w * 32 + lane];
        }
        float acc[8];
        {
            const __half2* h = reinterpret_cast<const __half2*>(&sv);
#pragma unroll
            for (int q = 0; q < 4; q++) {
                float2 f = __half22float2(h[q]);
                acc[2 * q] = f.x;
                acc[2 * q + 1] = f.y;
            }
        }
#pragma unroll
        for (int k = 0; k < KB; k++) {
            acc_row(acc, cv[k * 4 + 0], w[k].x);
            acc_row(acc, cv[k * 4 + 1], w[k].y);
            acc_row(acc, cv[k * 4 + 2], w[k].z);
            acc_row(acc, cv[k * 4 + 3], w[k].w);
        }
        __half2 o[4];
#pragma unroll
        for (int q = 0; q < 4; q++)
            o[q] = __floats2half2_rn(acc[2 * q], acc[2 * q + 1]);
        *(uint4*)(smh + px * SP_PITCH + lane * 8) = *reinterpret_cast<uint4*>(o);
    }
    __syncthreads();

    // ---- epilogue: fp16 transpose read -> f32 + bias, coalesced STG ----
    float* Ob = out + (size_t)b * C * HWS + p0;
    const float4* bias4 = (const float4*)g_bias2;
#pragma unroll
    for (int q = 0; q < 16; q++) {
        const int e = q * 256 + tid;
        const int colg = e >> 6;          // 0..63 (4-channel group)
        const int mm = e & 63;            // pixel within tile
        uint2 v16 = *(const uint2*)(smh + mm * SP_PITCH + colg * 4);
        float2 f0 = __half22float2(*reinterpret_cast<const __half2*>(&v16.x));
        float2 f1 = __half22float2(*reinterpret_cast<const __half2*>(&v16.y));
        float4 bi = __ldg(bias4 + colg);
        Ob[(size_t)(colg * 4 + 0) * HWS + mm] = f0.x + bi.x;
        Ob[(size_t)(colg * 4 + 1) * HWS + mm] = f0.y + bi.y;
        Ob[(size_t)(colg * 4 + 2) * HWS + mm] = f1.x + bi.z;
        Ob[(size_t)(colg * 4 + 3) * HWS + mm] = f1.y + bi.w;
    }
}

// ---------------- launch ----------------
extern "C" void kernel_launch(void* const* d_in, const int* in_sizes, int n_in,
                              void* d_out, int out_size) {
    (void)in_sizes; (void)n_in; (void)out_size;
    const float* x      = (const float*)d_in[0];
    const float* conv_w = (const float*)d_in[1];
    const float* conv_b = (const float*)d_in[2];
    const float* off_w  = (const float*)d_in[3];
    const float* off_b  = (const float*)d_in[4];
    const float* wgt_w  = (const float*)d_in[5];
    const float* wgt_b  = (const float*)d_in[6];
    const float* gamma  = (const float*)d_in[7];
    const float* beta   = (const float*)d_in[8];
    const float* rmean  = (const float*)d_in[9];
    const float* rvar   = (const float*)d_in[10];
    const float* out_w  = (const float*)d_in[11];
    const float* out_b  = (const float*)d_in[12];
    float* out = (float*)d_out;

    static bool attr_done = false;
    if (!attr_done) {
        cudaFuncSetAttribute(gemm1_mma, cudaFuncAttributeMaxDynamicSharedMemorySize, GEMM_SMEM);
        cudaFuncSetAttribute(sample_out, cudaFuncAttributeMaxDynamicSharedMemorySize, SAMPLE_SMEM);
        attr_done = true;
    }

    prep_kernel<<<C, C>>>(conv_w, conv_b, out_w, out_b, gamma, beta, rmean, rvar);
    gemm1_mma<<<dim3(HWS / 128, C / 128, BATCH), 256, GEMM_SMEM>>>(x);
    aux_kernel<<<NPX / 256, 256>>>(x, off_w, off_b, wgt_w, wgt_b);
    sample_out<<<dim3(HWS / SPX, BATCH), 256, SAMPLE_SMEM>>>(out);
}

// round 16
// speedup vs baseline: 1.3908x; 1.1261x over previous
#include <cuda_runtime.h>
#include <cuda_fp16.h>
#include <cstdint>

// Problem constants
#define BATCH 8
#define C 256
#define KB 4
#define HH 128
#define WW 128
#define HWS 16384
#define NPX (BATCH*HWS)

// ---------------- device scratch ----------------
__device__ __align__(16) __half g_Y[(size_t)NPX * C];   // Y = W2f*proj, fp16 [b][p][o]
__device__ __align__(16) __half g_wc[C * C];            // composed Wc = W2f*W1, fp16 [o][c]
__device__ float g_bcY[C];                              // composed bias for Y
__device__ float g_bias2[C];                            // final bias
__device__ float4 g_cw[(size_t)BATCH * KB * HWS];
__device__ int4   g_idx[(size_t)BATCH * KB * HWS];

// ---------------- helpers ----------------
__device__ __forceinline__ uint32_t smem_u32(const void* p) {
    uint32_t a;
    asm("{ .reg .u64 t; cvta.to.shared.u64 t, %1; cvt.u32.u64 %0, t; }" : "=r"(a) : "l"(p));
    return a;
}

__device__ __forceinline__ void ldsm4(uint32_t* r, uint32_t addr) {
    asm volatile("ldmatrix.sync.aligned.m8n8.x4.shared.b16 {%0,%1,%2,%3}, [%4];"
                 : "=r"(r[0]), "=r"(r[1]), "=r"(r[2]), "=r"(r[3]) : "r"(addr));
}

__device__ __forceinline__ void mma_fp16(float* d, const uint32_t* a, uint32_t b0, uint32_t b1) {
    asm volatile(
        "mma.sync.aligned.m16n8k16.row.col.f32.f16.f16.f32 "
        "{%0,%1,%2,%3}, {%4,%5,%6,%7}, {%8,%9}, {%0,%1,%2,%3};"
        : "+f"(d[0]), "+f"(d[1]), "+f"(d[2]), "+f"(d[3])
        : "r"(a[0]), "r"(a[1]), "r"(a[2]), "r"(a[3]), "r"(b0), "r"(b1));
}

// ============ GEMM (Y): tile 128x128, BK=32, 256 thr, 2 CTA/SM ============
#define ROWB 80
#define TSZ  (128 * ROWB)
#define BUFSZ (2 * TSZ)
#define OFF_A  0
#define OFF_B  TSZ
#define OFF_BIAS (2 * BUFSZ)
#define GEMM_SMEM (OFF_BIAS + 1024)

// ============ sample_out: 64 px x 256 ch fp16 tile, 256 thr, 5 CTA/SM ============
#define SPX 64
#define SP_PITCH 264                        // halves per row (528B, 16B-pad)
#define SAMPLE_SMEM (SPX * SP_PITCH * 2)    // 33792

// ---------------- prep: fold BN, compose Wc = W2f * W1, biases ----------------
__global__ void prep_kernel(const float* __restrict__ conv_w, const float* __restrict__ conv_b,
                            const float* __restrict__ out_w, const float* __restrict__ out_b,
                            const float* __restrict__ gamma, const float* __restrict__ beta,
                            const float* __restrict__ rmean, const float* __restrict__ rvar) {
    const int o = blockIdx.x;
    const int c = threadIdx.x;
    __shared__ float w2row[C];
    __shared__ float red[C];

    float inv = gamma[c] / sqrtf(rvar[c] + 1e-5f);
    float w = out_w[o * C + c];
    float w2f = w * inv;
    w2row[c] = w2f;
    red[c] = w * (beta[c] - rmean[c] * inv);
    __syncthreads();

    for (int s = 128; s > 0; s >>= 1) {
        if (c < s) red[c] += red[c + s];
        __syncthreads();
    }
    if (c == 0) g_bias2[o] = red[0] + out_b[o];
    __syncthreads();

    red[c] = w2row[c] * conv_b[c];
    __syncthreads();
    for (int s = 128; s > 0; s >>= 1) {
        if (c < s) red[c] += red[c + s];
        __syncthreads();
    }
    if (c == 0) g_bcY[o] = red[0];

    float acc = 0.f;
#pragma unroll 4
    for (int m = 0; m < C; m++)
        acc = fmaf(w2row[m], conv_w[m * C + c], acc);
    g_wc[o * C + c] = __float2half_rn(acc);
}

// ---------------- GEMM: Y[b][p][o] = x^T @ Wc^T + bcY ----------------
struct PF1 {
    uint32_t a[8];
    int4 b[2];
};

__device__ __forceinline__ void pf1_load(PF1& f, const float* __restrict__ xb,
                                         const __half* __restrict__ w,
                                         int kc, int am, int ach, int tid) {
#pragma unroll
    for (int i = 0; i < 8; i++) {
        int cl = ach * 16 + i * 2;
        float v0 = xb[(size_t)(kc + cl) * HWS + am];
        float v1 = xb[(size_t)(kc + cl + 1) * HWS + am];
        __half2 h = __floats2half2_rn(v0, v1);
        f.a[i] = *reinterpret_cast<uint32_t*>(&h);
    }
#pragma unroll
    for (int j = 0; j < 2; j++) {
        int e = j * 256 + tid;
        int row = e >> 2, ch = e & 3;
        f.b[j] = *(const int4*)(w + (size_t)row * C + kc + ch * 8);
    }
}

__device__ __forceinline__ void pf1_store(const PF1& f, char* base, int am, int ach, int tid) {
#pragma unroll
    for (int i = 0; i < 8; i++) {
        int cl = ach * 16 + i * 2;
        *(uint32_t*)(base + OFF_A + am * ROWB + cl * 2) = f.a[i];
    }
#pragma unroll
    for (int j = 0; j < 2; j++) {
        int e = j * 256 + tid;
        int row = e >> 2, ch = e & 3;
        *(int4*)(base + OFF_B + row * ROWB + ch * 16) = f.b[j];
    }
}

__global__ __launch_bounds__(256) void gemm1_mma(const float* __restrict__ x) {
    extern __shared__ char sm[];
    const uint32_t smb = smem_u32(sm);
    const int tid = threadIdx.x;
    const int wid = tid >> 5, lane = tid & 31;
    const int warp_m = wid & 3, warp_n = wid >> 2;
    const int lr = lane & 15, lc = lane >> 4;
    const int p0 = blockIdx.x * 128, o0 = blockIdx.y * 128, b = blockIdx.z;

    if (tid < 128) ((float*)(sm + OFF_BIAS))[tid] = g_bcY[o0 + tid];

    const float* xb = x + (size_t)b * C * HWS + p0;
    const __half* w = g_wc + (size_t)o0 * C;
    const int am = tid & 127, ach = tid >> 7;

    float acc[2][8][4];
#pragma unroll
    for (int t = 0; t < 2; t++)
#pragma unroll
        for (int j = 0; j < 8; j++)
#pragma unroll
            for (int q = 0; q < 4; q++) acc[t][j][q] = 0.f;

    PF1 f;
    pf1_load(f, xb, w, 0, am, ach, tid);
    pf1_store(f, sm, am, ach, tid);
    __syncthreads();

    for (int kt = 0; kt < 8; kt++) {
        const int buf = kt & 1;
        if (kt < 7) pf1_load(f, xb, w, (kt + 1) * 32, am, ach, tid);
        {
            const uint32_t smbuf = smb + buf * BUFSZ;
            const uint32_t a_base = smbuf + OFF_A + (uint32_t)(warp_m * 32 + lr) * ROWB + lc * 16;
            const uint32_t b_base = smbuf + OFF_B + (uint32_t)(warp_n * 64 + lr) * ROWB + lc * 16;
#pragma unroll
            for (int s = 0; s < 2; s++) {
                uint32_t a[2][4], bb[4][4];
#pragma unroll
                for (int t = 0; t < 2; t++)
                    ldsm4(a[t], a_base + t * (16 * ROWB) + s * 32);
#pragma unroll
                for (int u = 0; u < 4; u++)
                    ldsm4(bb[u], b_base + u * (16 * ROWB) + s * 32);
#pragma unroll
                for (int t = 0; t < 2; t++)
#pragma unroll
                    for (int u = 0; u < 4; u++) {
                        mma_fp16(acc[t][u * 2], a[t], bb[u][0], bb[u][2]);
                        mma_fp16(acc[t][u * 2 + 1], a[t], bb[u][1], bb[u][3]);
                    }
            }
        }
        if (kt < 7) {
            pf1_store(f, sm + (buf ^ 1) * BUFSZ, am, ach, tid);
            __syncthreads();
        }
    }

    // epilogue: write Y fp16 [b][p][o] + bcY
    const float* sbias = (const float*)(sm + OFF_BIAS);
    __half* Cb = g_Y + ((size_t)b * HWS + p0) * C + o0;
    const int g4 = lane >> 2, tg = lane & 3;
#pragma unroll
    for (int t = 0; t < 2; t++) {
        const int r0 = warp_m * 32 + t * 16 + g4;
#pragma unroll
        for (int j = 0; j < 8; j++) {
            const int oc = warp_n * 64 + j * 8 + tg * 2;
            float b0 = sbias[oc], b1 = sbias[oc + 1];
            __half2 v0 = __floats2half2_rn(acc[t][j][0] + b0, acc[t][j][1] + b1);
            __half2 v1 = __floats2half2_rn(acc[t][j][2] + b0, acc[t][j][3] + b1);
            *(uint32_t*)(Cb + (size_t)r0 * C + oc) = *reinterpret_cast<uint32_t*>(&v0);
            *(uint32_t*)(Cb + (size_t)(r0 + 8) * C + oc) = *reinterpret_cast<uint32_t*>(&v1);
        }
    }
}

// ---------------- aux: direct-global GEMV, 1 px/thread ----------------
__global__ __launch_bounds__(256) void aux_kernel(
        const float* __restrict__ x,
        const float* __restrict__ off_w, const float* __restrict__ off_b,
        const float* __restrict__ wgt_w, const float* __restrict__ wgt_b) {
    __shared__ float wsi[C * 12];
    const int tid = threadIdx.x;
    const int pp = blockIdx.x * 256 + tid;
    const int b = pp >> 14;
    const int p = pp & 16383;

    for (int e = tid; e < 2 * C * KB; e += 256) {
        int kd = e >> 8, c = e & 255;
        wsi[c * 12 + kd] = off_w[e];
    }
    for (int e = tid; e < C * KB; e += 256) {
        int k = e >> 8, c = e & 255;
        wsi[c * 12 + 8 + k] = wgt_w[e];
    }
    __syncthreads();

    float acc[12];
#pragma unroll
    for (int j = 0; j < 12; j++) acc[j] = 0.f;

    const float* xb = x + (size_t)b * C * HWS + p;
#pragma unroll 4
    for (int c = 0; c < C; c++) {
        float xv = xb[(size_t)c * HWS];
        const float4* wp = (const float4*)(wsi + c * 12);
        float4 wa = wp[0], wb = wp[1], wc = wp[2];
        acc[0] = fmaf(xv, wa.x, acc[0]);  acc[1] = fmaf(xv, wa.y, acc[1]);
        acc[2] = fmaf(xv, wa.z, acc[2]);  acc[3] = fmaf(xv, wa.w, acc[3]);
        acc[4] = fmaf(xv, wb.x, acc[4]);  acc[5] = fmaf(xv, wb.y, acc[5]);
        acc[6] = fmaf(xv, wb.z, acc[6]);  acc[7] = fmaf(xv, wb.w, acc[7]);
        acc[8] = fmaf(xv, wc.x, acc[8]);  acc[9] = fmaf(xv, wc.y, acc[9]);
        acc[10] = fmaf(xv, wc.z, acc[10]); acc[11] = fmaf(xv, wc.w, acc[11]);
    }

    const int py = p >> 7, px = p & 127;
    float l0 = acc[8] + wgt_b[0], l1 = acc[9] + wgt_b[1];
    float l2 = acc[10] + wgt_b[2], l3 = acc[11] + wgt_b[3];
    float mx = fmaxf(fmaxf(l0, l1), fmaxf(l2, l3));
    float e0 = __expf(l0 - mx), e1 = __expf(l1 - mx);
    float e2 = __expf(l2 - mx), e3 = __expf(l3 - mx);
    float invs = 1.f / (e0 + e1 + e2 + e3);
    float wk4[4] = {e0 * invs, e1 * invs, e2 * invs, e3 * invs};
#pragma unroll
    for (int k = 0; k < KB; k++) {
        float vx = (float)px + acc[2 * k] + off_b[2 * k];
        float vy = (float)py + acc[2 * k + 1] + off_b[2 * k + 1];
        float x0f = floorf(vx), y0f = floorf(vy);
        float wx1 = vx - x0f, wy1 = vy - y0f;
        int x0 = (int)x0f, y0 = (int)y0f;
        bool vx0 = (x0 >= 0) && (x0 <= WW - 1);
        bool vx1 = (x0 + 1 >= 0) && (x0 + 1 <= WW - 1);
        bool vy0 = (y0 >= 0) && (y0 <= HH - 1);
        bool vy1 = (y0 + 1 >= 0) && (y0 + 1 <= HH - 1);
        float wk = wk4[k];
        float w00 = (1.f - wx1) * (1.f - wy1) * wk * (float)(vx0 && vy0);
        float w01 = wx1 * (1.f - wy1) * wk * (float)(vx1 && vy0);
        float w10 = (1.f - wx1) * wy1 * wk * (float)(vx0 && vy1);
        float w11 = wx1 * wy1 * wk * (float)(vx1 && vy1);
        int xc0 = min(max(x0, 0), WW - 1);
        int xc1 = min(max(x0 + 1, 0), WW - 1);
        int yc0 = min(max(y0, 0), HH - 1);
        int yc1 = min(max(y0 + 1, 0), HH - 1);
        size_t off = ((size_t)(b * KB + k)) * HWS + p;
        g_idx[off] = make_int4(yc0 * WW + xc0, yc0 * WW + xc1,
                               yc1 * WW + xc0, yc1 * WW + xc1);
        g_cw[off] = make_float4(w00, w01, w10, w11);
    }
}

// ---------------- sample_out: out[b][o][p] = Y[p] + sum w*Y[idx] + bias2 ----------------
__device__ __forceinline__ void acc_row(float* acc, uint4 v, float w) {
    const __half2* h = reinterpret_cast<const __half2*>(&v);
#pragma unroll
    for (int i = 0; i < 4; i++) {
        float2 f = __half22float2(h[i]);
        acc[2 * i]     = fmaf(w, f.x, acc[2 * i]);
        acc[2 * i + 1] = fmaf(w, f.y, acc[2 * i + 1]);
    }
}

__global__ __launch_bounds__(256) void sample_out(float* __restrict__ out) {
    extern __shared__ __half smh[];
    const int tid = threadIdx.x;
    const int wid = tid >> 5, lane = tid & 31;
    const int p0 = blockIdx.x * SPX, b = blockIdx.y;

    // ---- gather phase: out-tile [64 px][256 ch] fp16 into smem ----
    const uint4* Yb = (const uint4*)g_Y + (size_t)b * HWS * 32;
#pragma unroll
    for (int i = 0; i < 8; i++) {
        const int px = wid * 8 + i;
        const int p = p0 + px;
        const size_t kb = (size_t)b * KB * HWS + p;

        int4 id[KB];
        float4 w[KB];
#pragma unroll
        for (int k = 0; k < KB; k++) {
            id[k] = g_idx[kb + (size_t)k * HWS];
            w[k] = g_cw[kb + (size_t)k * HWS];
        }
        uint4 sv = Yb[(size_t)p * 32 + lane];
        uint4 cv[KB * 4];
#pragma unroll
        for (int k = 0; k < KB; k++) {
            cv[k * 4 + 0] = Yb[(size_t)id[k].x * 32 + lane];
            cv[k * 4 + 1] = Yb[(size_t)id[k].y * 32 + lane];
            cv[k * 4 + 2] = Yb[(size_t)id[k].z * 32 + lane];
            cv[k * 4 + 3] = Yb[(size_t)id[k].w * 32 + lane];
        }
        float acc[8];
        {
            const __half2* h = reinterpret_cast<const __half2*>(&sv);
#pragma unroll
            for (int q = 0; q < 4; q++) {
                float2 f = __half22float2(h[q]);
                acc[2 * q] = f.x;
                acc[2 * q + 1] = f.y;
            }
        }
#pragma unroll
        for (int k = 0; k < KB; k++) {
            acc_row(acc, cv[k * 4 + 0], w[k].x);
            acc_row(acc, cv[k * 4 + 1], w[k].y);
            acc_row(acc, cv[k * 4 + 2], w[k].z);
            acc_row(acc, cv[k * 4 + 3], w[k].w);
        }
        __half2 o[4];
#pragma unroll
        for (int q = 0; q < 4; q++)
            o[q] = __floats2half2_rn(acc[2 * q], acc[2 * q + 1]);
        *(uint4*)(smh + px * SP_PITCH + lane * 8) = *reinterpret_cast<uint4*>(o);
    }
    __syncthreads();

    // ---- epilogue: fp16 transpose read -> f32 + bias, coalesced STG ----
    float* Ob = out + (size_t)b * C * HWS + p0;
    const float4* bias4 = (const float4*)g_bias2;
#pragma unroll
    for (int q = 0; q < 16; q++) {
        const int e = q * 256 + tid;
        const int colg = e >> 6;          // 0..63 (4-channel group)
        const int mm = e & 63;            // pixel within tile
        uint2 v16 = *(const uint2*)(smh + mm * SP_PITCH + colg * 4);
        float2 f0 = __half22float2(*reinterpret_cast<const __half2*>(&v16.x));
        float2 f1 = __half22float2(*reinterpret_cast<const __half2*>(&v16.y));
        float4 bi = __ldg(bias4 + colg);
        Ob[(size_t)(colg * 4 + 0) * HWS + mm] = f0.x + bi.x;
        Ob[(size_t)(colg * 4 + 1) * HWS + mm] = f0.y + bi.y;
        Ob[(size_t)(colg * 4 + 2) * HWS + mm] = f1.x + bi.z;
        Ob[(size_t)(colg * 4 + 3) * HWS + mm] = f1.y + bi.w;
    }
}

// ---------------- launch: aux on side stream, overlapped with prep+gemm1 ----------------
extern "C" void kernel_launch(void* const* d_in, const int* in_sizes, int n_in,
                              void* d_out, int out_size) {
    (void)in_sizes; (void)n_in; (void)out_size;
    const float* x      = (const float*)d_in[0];
    const float* conv_w = (const float*)d_in[1];
    const float* conv_b = (const float*)d_in[2];
    const float* off_w  = (const float*)d_in[3];
    const float* off_b  = (const float*)d_in[4];
    const float* wgt_w  = (const float*)d_in[5];
    const float* wgt_b  = (const float*)d_in[6];
    const float* gamma  = (const float*)d_in[7];
    const float* beta   = (const float*)d_in[8];
    const float* rmean  = (const float*)d_in[9];
    const float* rvar   = (const float*)d_in[10];
    const float* out_w  = (const float*)d_in[11];
    const float* out_b  = (const float*)d_in[12];
    float* out = (float*)d_out;

    static bool init_done = false;
    static cudaStream_t s2;
    static cudaEvent_t ev_fork, ev_join;
    if (!init_done) {
        cudaFuncSetAttribute(gemm1_mma, cudaFuncAttributeMaxDynamicSharedMemorySize, GEMM_SMEM);
        cudaFuncSetAttribute(sample_out, cudaFuncAttributeMaxDynamicSharedMemorySize, SAMPLE_SMEM);
        cudaStreamCreateWithFlags(&s2, cudaStreamNonBlocking);
        cudaEventCreateWithFlags(&ev_fork, cudaEventDisableTiming);
        cudaEventCreateWithFlags(&ev_join, cudaEventDisableTiming);
        init_done = true;
    }

    // fork: aux runs on s2, parallel with prep+gemm1 on the main stream
    cudaEventRecord(ev_fork, 0);
    cudaStreamWaitEvent(s2, ev_fork, 0);
    aux_kernel<<<NPX / 256, 256, 0, s2>>>(x, off_w, off_b, wgt_w, wgt_b);
    cudaEventRecord(ev_join, s2);

    prep_kernel<<<C, C>>>(conv_w, conv_b, out_w, out_b, gamma, beta, rmean, rvar);
    gemm1_mma<<<dim3(HWS / 128, C / 128, BATCH), 256, GEMM_SMEM>>>(x);

    // join: sample_out needs both gemm1 (Y) and aux (idx/cw)
    cudaStreamWaitEvent(0, ev_join, 0);
    sample_out<<<dim3(HWS / SPX, BATCH), 256, SAMPLE_SMEM>>>(out);
}